// round 4
// baseline (speedup 1.0000x reference)
#include <cuda_runtime.h>
#include <cuda_bf16.h>
#include <math.h>
#include <stdint.h>
#include <string.h>

#define B_ 32
#define S_ 2048
#define D_ 1024

// ---------------------------------------------------------------------------
// Device-global scratch
// ---------------------------------------------------------------------------
__device__ float g_pd[B_ * D_];                      // proj_dec + Wc_b
__device__ float g_score[B_ * S_];                   // pre-softmax scores
__device__ __align__(16) __nv_bfloat16 g_Uhi[D_ * D_];   // U^T hi  [u][d]
__device__ __align__(16) __nv_bfloat16 g_Ulo[D_ * D_];   // U^T lo  [u][d]
__device__ __align__(16) __nv_bfloat16 g_Ehi[(size_t)B_ * S_ * D_];
__device__ __align__(16) __nv_bfloat16 g_Elo[(size_t)B_ * S_ * D_];

// ---------------------------------------------------------------------------
// Helpers (baseline-ISA only: valid on .target sm_103)
// ---------------------------------------------------------------------------
__device__ __forceinline__ uint32_t smem_u32(const void* p) {
    uint32_t a;
    asm("{ .reg .u64 t; cvta.to.shared.u64 t, %1; cvt.u32.u64 %0, t; }"
        : "=r"(a) : "l"(p));
    return a;
}
__device__ __forceinline__ void cpa16(uint32_t dst, const void* src) {
    asm volatile("cp.async.cg.shared.global [%0], [%1], 16;" :: "r"(dst), "l"(src));
}
__device__ __forceinline__ void ldsm4(uint32_t* r, uint32_t addr) {
    asm volatile("ldmatrix.sync.aligned.m8n8.x4.shared.b16 {%0,%1,%2,%3}, [%4];"
                 : "=r"(r[0]), "=r"(r[1]), "=r"(r[2]), "=r"(r[3]) : "r"(addr));
}
__device__ __forceinline__ void mma16816(float* c, const uint32_t* a, const uint32_t* b) {
    asm volatile("mma.sync.aligned.m16n8k16.row.col.f32.bf16.bf16.f32 "
                 "{%0,%1,%2,%3}, {%4,%5,%6,%7}, {%8,%9}, {%0,%1,%2,%3};"
                 : "+f"(c[0]), "+f"(c[1]), "+f"(c[2]), "+f"(c[3])
                 : "r"(a[0]), "r"(a[1]), "r"(a[2]), "r"(a[3]), "r"(b[0]), "r"(b[1]));
}
#define SW128(o) ((o) ^ (((o) >> 3) & 0x70))

__device__ __forceinline__ uint32_t pk(__nv_bfloat16 a, __nv_bfloat16 b) {
    __nv_bfloat162 t = __halves2bfloat162(a, b);
    uint32_t r; memcpy(&r, &t, 4); return r;
}

// ---------------------------------------------------------------------------
// Kernel P1: g_pd[b,u] = h[b] @ W[:,u] + Wc_b[u]
// ---------------------------------------------------------------------------
__global__ void proj_dec_kernel(const float* __restrict__ h,
                                const float* __restrict__ W,
                                const float* __restrict__ Wc_b) {
    __shared__ float sh[D_];
    const int b = blockIdx.y;
    const int u = blockIdx.x * 128 + threadIdx.x;
    for (int i = threadIdx.x; i < D_; i += 128) sh[i] = h[b * D_ + i];
    __syncthreads();
    float a0 = 0.f, a1 = 0.f, a2 = 0.f, a3 = 0.f;
    #pragma unroll 8
    for (int k = 0; k < D_; k += 4) {
        a0 += sh[k + 0] * W[(size_t)(k + 0) * D_ + u];
        a1 += sh[k + 1] * W[(size_t)(k + 1) * D_ + u];
        a2 += sh[k + 2] * W[(size_t)(k + 2) * D_ + u];
        a3 += sh[k + 3] * W[(size_t)(k + 3) * D_ + u];
    }
    g_pd[b * D_ + u] = (a0 + a1) + (a2 + a3) + Wc_b[u];
}

// ---------------------------------------------------------------------------
// Kernel P2: bf16-split E -> g_Ehi/g_Elo
// ---------------------------------------------------------------------------
__global__ void esplit_kernel(const float* __restrict__ E) {
    size_t i = (size_t)blockIdx.x * 256 + threadIdx.x;
    const float4* E4 = (const float4*)E;
    float4 v0 = E4[2 * i], v1 = E4[2 * i + 1];
    float v[8] = {v0.x, v0.y, v0.z, v0.w, v1.x, v1.y, v1.z, v1.w};
    __nv_bfloat16 h[8], l[8];
    #pragma unroll
    for (int j = 0; j < 8; j++) {
        h[j] = __float2bfloat16_rn(v[j]);
        l[j] = __float2bfloat16_rn(v[j] - __bfloat162float(h[j]));
    }
    uint4 wh = {pk(h[0], h[1]), pk(h[2], h[3]), pk(h[4], h[5]), pk(h[6], h[7])};
    uint4 wl = {pk(l[0], l[1]), pk(l[2], l[3]), pk(l[4], l[5]), pk(l[6], l[7])};
    ((uint4*)g_Ehi)[i] = wh;
    ((uint4*)g_Elo)[i] = wl;
}

// ---------------------------------------------------------------------------
// Kernel P3: transpose + bf16-split U:  g_Uhi/g_Ulo[u][d]
// ---------------------------------------------------------------------------
__global__ void usplit_kernel(const float* __restrict__ U) {
    __shared__ float t[32][33];
    const int u0 = blockIdx.x * 32, d0 = blockIdx.y * 32;
    const int tx = threadIdx.x, ty = threadIdx.y;   // 32 x 8
    #pragma unroll
    for (int r = 0; r < 32; r += 8)
        t[ty + r][tx] = U[(size_t)(d0 + ty + r) * D_ + u0 + tx];
    __syncthreads();
    #pragma unroll
    for (int r = 0; r < 32; r += 8) {
        float v = t[tx][ty + r];
        int u = u0 + ty + r, d = d0 + tx;
        __nv_bfloat16 hi = __float2bfloat16_rn(v);
        __nv_bfloat16 lo = __float2bfloat16_rn(v - __bfloat162float(hi));
        g_Uhi[(size_t)u * D_ + d] = hi;
        g_Ulo[(size_t)u * D_ + d] = lo;
    }
}

// ---------------------------------------------------------------------------
// Kernel B: HMMA score GEMM + fused tanh.V epilogue.
// CTA = 128 s x 256 u-chunk (4 chunks looped), K in 32-wide chunks,
// 4-stage cp.async pipeline, 512 threads (16 warps, warp tile 64x32).
// Stage = A 16KB (128x[hi32|lo32]) + B 32KB (256x[hi32|lo32]).
// ---------------------------------------------------------------------------
#define KC     32
#define STAGE  49152          // 48 KB
#define NITER  128            // 4 n-chunks * 32 k-chunks

__global__ __launch_bounds__(512, 1)
void score_mma_kernel(const float* __restrict__ cov,
                      const float* __restrict__ Wc_w,
                      const float* __restrict__ Vv) {
    extern __shared__ __align__(128) char dyn[];
    __shared__ float s_pd[D_], s_wc[D_], s_v[D_];
    __shared__ float red[8][128];

    const int tid = threadIdx.x, lane = tid & 31, wid = tid >> 5;
    const int warp_m = wid >> 3, warp_n = wid & 7;
    const int wm0 = warp_m * 64, wn0 = warp_n * 32;
    const int b = blockIdx.y, s0 = blockIdx.x * 128;
    const uint32_t sb = smem_u32(dyn);

    for (int i = tid; i < D_; i += 512) {
        s_pd[i] = g_pd[b * D_ + i];
        s_wc[i] = Wc_w[i];
        s_v[i]  = Vv[i];
    }

    const __nv_bfloat16* Eh = g_Ehi + (size_t)(b * S_ + s0) * D_;
    const __nv_bfloat16* El = g_Elo + (size_t)(b * S_ + s0) * D_;

    // ldmatrix per-thread geometry (validated in R3)
    const int arow = ((lane >> 3) & 1) * 8 + (lane & 7);
    const int acol = (lane >> 4);
    const int brow = ((lane >> 4) & 1) * 8 + (lane & 7);
    const int bcol = (lane >> 3) & 1;

    float covr[4][2];
    #pragma unroll
    for (int mi = 0; mi < 4; mi++)
        #pragma unroll
        for (int h = 0; h < 2; h++)
            covr[mi][h] = cov[b * S_ + s0 + wm0 + mi * 16 + (lane >> 2) + 8 * h];

    float acc[4][4][4];
    #pragma unroll
    for (int mi = 0; mi < 4; mi++)
        #pragma unroll
        for (int ni = 0; ni < 4; ni++)
            #pragma unroll
            for (int q = 0; q < 4; q++) acc[mi][ni][q] = 0.f;
    float rs[4][2];
    #pragma unroll
    for (int mi = 0; mi < 4; mi++) { rs[mi][0] = 0.f; rs[mi][1] = 0.f; }

    auto load_tiles = [&](int it) {
        const int nb = it >> 5, kc = it & 31;
        const uint32_t stg = sb + (uint32_t)(it & 3) * STAGE;
        const __nv_bfloat16* Ehk = Eh + kc * KC;
        const __nv_bfloat16* Elk = El + kc * KC;
        const __nv_bfloat16* Uhk = g_Uhi + (size_t)(nb * 256) * D_ + kc * KC;
        const __nv_bfloat16* Ulk = g_Ulo + (size_t)(nb * 256) * D_ + kc * KC;
        #pragma unroll
        for (int i = 0; i < 2; i++) {           // A: 1024 x 16B chunks
            int id = tid + i * 512;
            int r = id >> 3, c = id & 7;
            uint32_t off = SW128((uint32_t)(r * 128 + c * 16));
            const void* src = (c < 4) ? (const void*)(Ehk + (size_t)r * D_ + c * 8)
                                      : (const void*)(Elk + (size_t)r * D_ + (c - 4) * 8);
            cpa16(stg + off, src);
        }
        #pragma unroll
        for (int i = 0; i < 4; i++) {           // B: 2048 x 16B chunks
            int id = tid + i * 512;
            int r = id >> 3, c = id & 7;
            uint32_t off = SW128((uint32_t)(r * 128 + c * 16));
            const void* src = (c < 4) ? (const void*)(Uhk + (size_t)r * D_ + c * 8)
                                      : (const void*)(Ulk + (size_t)r * D_ + (c - 4) * 8);
            cpa16(stg + 16384 + off, src);
        }
        asm volatile("cp.async.commit_group;" ::: "memory");
    };

    load_tiles(0);
    load_tiles(1);
    load_tiles(2);

    for (int it = 0; it < NITER; it++) {
        asm volatile("cp.async.wait_group 2;" ::: "memory");
        __syncthreads();
        if (it + 3 < NITER) load_tiles(it + 3);
        else asm volatile("cp.async.commit_group;" ::: "memory");  // keep group count uniform

        const uint32_t stg = sb + (uint32_t)(it & 3) * STAGE;
        #pragma unroll
        for (int ks = 0; ks < 2; ks++) {
            uint32_t a[4][4], bh[2][4], bl[2][4];
            #pragma unroll
            for (int mi = 0; mi < 4; mi++) {    // A hi
                uint32_t off = (uint32_t)((wm0 + mi * 16 + arow) * 128 + ks * 32 + acol * 16);
                ldsm4(a[mi], stg + SW128(off));
            }
            #pragma unroll
            for (int np = 0; np < 2; np++) {    // B hi
                uint32_t off = (uint32_t)((wn0 + np * 16 + brow) * 128 + ks * 32 + bcol * 16);
                ldsm4(bh[np], stg + 16384 + SW128(off));
            }
            #pragma unroll
            for (int mi = 0; mi < 4; mi++)
                #pragma unroll
                for (int ni = 0; ni < 4; ni++)
                    mma16816(acc[mi][ni], a[mi], &bh[ni >> 1][(ni & 1) * 2]);
            #pragma unroll
            for (int np = 0; np < 2; np++) {    // B lo
                uint32_t off = (uint32_t)((wn0 + np * 16 + brow) * 128 + 64 + ks * 32 + bcol * 16);
                ldsm4(bl[np], stg + 16384 + SW128(off));
            }
            #pragma unroll
            for (int mi = 0; mi < 4; mi++)
                #pragma unroll
                for (int ni = 0; ni < 4; ni++)
                    mma16816(acc[mi][ni], a[mi], &bl[ni >> 1][(ni & 1) * 2]);
            #pragma unroll
            for (int mi = 0; mi < 4; mi++) {    // A lo (overwrite hi frags)
                uint32_t off = (uint32_t)((wm0 + mi * 16 + arow) * 128 + 64 + ks * 32 + acol * 16);
                ldsm4(a[mi], stg + SW128(off));
            }
            #pragma unroll
            for (int mi = 0; mi < 4; mi++)
                #pragma unroll
                for (int ni = 0; ni < 4; ni++)
                    mma16816(acc[mi][ni], a[mi], &bh[ni >> 1][(ni & 1) * 2]);
        }

        if ((it & 31) == 31) {                  // epilogue for this u-chunk of 256
            const int nb = it >> 5;
            #pragma unroll
            for (int mi = 0; mi < 4; mi++)
                #pragma unroll
                for (int ni = 0; ni < 4; ni++)
                    #pragma unroll
                    for (int h = 0; h < 2; h++)
                        #pragma unroll
                        for (int j = 0; j < 2; j++) {
                            int u = nb * 256 + wn0 + ni * 8 + (lane & 3) * 2 + j;
                            float x = acc[mi][ni][h * 2 + j] + s_pd[u] + covr[mi][h] * s_wc[u];
                            rs[mi][h] += tanhf(x) * s_v[u];
                            acc[mi][ni][h * 2 + j] = 0.f;
                        }
        }
    }

    // reduce over lane quads (cols), then across warp_n via smem
    #pragma unroll
    for (int mi = 0; mi < 4; mi++)
        #pragma unroll
        for (int h = 0; h < 2; h++) {
            float v = rs[mi][h];
            v += __shfl_xor_sync(0xffffffffu, v, 1);
            v += __shfl_xor_sync(0xffffffffu, v, 2);
            if ((lane & 3) == 0)
                red[warp_n][wm0 + mi * 16 + (lane >> 2) + 8 * h] = v;
        }
    __syncthreads();
    if (tid < 128) {
        float s = 0.f;
        #pragma unroll
        for (int w = 0; w < 8; w++) s += red[w][tid];
        g_score[b * S_ + s0 + tid] = s;
    }
}

// ---------------------------------------------------------------------------
// Kernel C: masked softmax + renorm + coverage out
// ---------------------------------------------------------------------------
__global__ void softmax_kernel(const float* __restrict__ mask,
                               const float* __restrict__ cov,
                               float* __restrict__ out) {
    __shared__ float sh[S_];
    __shared__ float red[256];
    const int b = blockIdx.x, tid = threadIdx.x;

    float mx = -1e30f;
    for (int s = tid; s < S_; s += 256) {
        float v = g_score[b * S_ + s];
        sh[s] = v;
        if (mask[b * S_ + s] > 0.f) mx = fmaxf(mx, v);
    }
    red[tid] = mx; __syncthreads();
    for (int o = 128; o; o >>= 1) {
        if (tid < o) red[tid] = fmaxf(red[tid], red[tid + o]);
        __syncthreads();
    }
    mx = red[0]; __syncthreads();

    float psum = 0.f;
    for (int s = tid; s < S_; s += 256) {
        float e = mask[b * S_ + s] * expf(sh[s] - mx);
        sh[s] = e;
        psum += e;
    }
    red[tid] = psum; __syncthreads();
    for (int o = 128; o; o >>= 1) {
        if (tid < o) red[tid] += red[tid + o];
        __syncthreads();
    }
    const float inv = 1.f / red[0];

    float* attn = out + B_ * D_;
    float* covo = out + B_ * D_ + B_ * S_;
    for (int s = tid; s < S_; s += 256) {
        float a = sh[s] * inv;
        attn[b * S_ + s] = a;
        covo[b * S_ + s] = cov[b * S_ + s] + a;
    }
}

// ---------------------------------------------------------------------------
// Kernel D: context[b,d] = sum_s attn[b,s] * E[b,s,d]   (float4 loads)
// block = 256 thr = 32 d-quads (128 d) x 8 s-slices; grid (8 d-tiles, 32 b)
// ---------------------------------------------------------------------------
__global__ void context_kernel(const float* __restrict__ E,
                               const float* __restrict__ out_attn,
                               float* __restrict__ ctx) {
    __shared__ float shA[S_];
    __shared__ float4 red4[256];
    const int b  = blockIdx.y;
    const int dq = threadIdx.x & 31;
    const int ts = threadIdx.x >> 5;   // 0..7
    const int d  = blockIdx.x * 128 + dq * 4;

    for (int s = threadIdx.x; s < S_; s += 256)
        shA[s] = out_attn[b * S_ + s];
    __syncthreads();

    float4 acc = {0.f, 0.f, 0.f, 0.f};
    #pragma unroll 4
    for (int s = ts; s < S_; s += 8) {
        float a = shA[s];
        float4 e = *(const float4*)(E + ((size_t)(b * S_ + s)) * D_ + d);
        acc.x += a * e.x; acc.y += a * e.y; acc.z += a * e.z; acc.w += a * e.w;
    }
    red4[threadIdx.x] = acc;
    __syncthreads();
    if (ts == 0) {
        float4 r = red4[dq];
        #pragma unroll
        for (int w = 1; w < 8; w++) {
            float4 t = red4[dq + w * 32];
            r.x += t.x; r.y += t.y; r.z += t.z; r.w += t.w;
        }
        *(float4*)(ctx + b * D_ + d) = r;
    }
}

// ---------------------------------------------------------------------------
extern "C" void kernel_launch(void* const* d_in, const int* in_sizes, int n_in,
                              void* d_out, int out_size) {
    const float* E    = (const float*)d_in[0];
    const float* mask = (const float*)d_in[1];
    const float* h    = (const float*)d_in[2];
    const float* cov  = (const float*)d_in[3];
    const float* W    = (const float*)d_in[4];
    const float* U    = (const float*)d_in[5];
    const float* Wc_w = (const float*)d_in[6];
    const float* Wc_b = (const float*)d_in[7];
    const float* V    = (const float*)d_in[8];
    float* out = (float*)d_out;

    cudaFuncSetAttribute(score_mma_kernel,
                         cudaFuncAttributeMaxDynamicSharedMemorySize, 4 * STAGE);

    esplit_kernel<<<32768, 256>>>(E);
    usplit_kernel<<<dim3(32, 32), dim3(32, 8)>>>(U);
    proj_dec_kernel<<<dim3(D_ / 128, B_), 128>>>(h, W, Wc_b);
    score_mma_kernel<<<dim3(S_ / 128, B_), 512, 4 * STAGE>>>(cov, Wc_w, V);
    softmax_kernel<<<B_, 256>>>(mask, cov, out);
    context_kernel<<<dim3(8, B_), 256>>>(E, out + B_ * D_, out);
}

// round 5
// speedup vs baseline: 1.2610x; 1.2610x over previous
#include <cuda_runtime.h>
#include <cuda_bf16.h>
#include <math.h>
#include <stdint.h>
#include <string.h>

#define B_ 32
#define S_ 2048
#define D_ 1024

// ---------------------------------------------------------------------------
// Device-global scratch
// ---------------------------------------------------------------------------
__device__ float g_pd[B_ * D_];                      // proj_dec + Wc_b
__device__ float g_spart[4 * B_ * S_];               // partial scores (per u-block)
__device__ __align__(16) __nv_bfloat16 g_Uhi[D_ * D_];   // U^T hi  [u][d]
__device__ __align__(16) __nv_bfloat16 g_Ulo[D_ * D_];   // U^T lo  [u][d]
__device__ __align__(16) __nv_bfloat16 g_Ehi[(size_t)B_ * S_ * D_];
__device__ __align__(16) __nv_bfloat16 g_Elo[(size_t)B_ * S_ * D_];

// ---------------------------------------------------------------------------
// Helpers (baseline-ISA only: valid on .target sm_103)
// ---------------------------------------------------------------------------
__device__ __forceinline__ uint32_t smem_u32(const void* p) {
    uint32_t a;
    asm("{ .reg .u64 t; cvta.to.shared.u64 t, %1; cvt.u32.u64 %0, t; }"
        : "=r"(a) : "l"(p));
    return a;
}
__device__ __forceinline__ void cpa16(uint32_t dst, const void* src) {
    asm volatile("cp.async.cg.shared.global [%0], [%1], 16;" :: "r"(dst), "l"(src));
}
__device__ __forceinline__ void ldsm4(uint32_t* r, uint32_t addr) {
    asm volatile("ldmatrix.sync.aligned.m8n8.x4.shared.b16 {%0,%1,%2,%3}, [%4];"
                 : "=r"(r[0]), "=r"(r[1]), "=r"(r[2]), "=r"(r[3]) : "r"(addr));
}
__device__ __forceinline__ void mma16816(float* c, const uint32_t* a, const uint32_t* b) {
    asm volatile("mma.sync.aligned.m16n8k16.row.col.f32.bf16.bf16.f32 "
                 "{%0,%1,%2,%3}, {%4,%5,%6,%7}, {%8,%9}, {%0,%1,%2,%3};"
                 : "+f"(c[0]), "+f"(c[1]), "+f"(c[2]), "+f"(c[3])
                 : "r"(a[0]), "r"(a[1]), "r"(a[2]), "r"(a[3]), "r"(b[0]), "r"(b[1]));
}
#define SW128(o) ((o) ^ (((o) >> 3) & 0x70))

__device__ __forceinline__ uint32_t pk(__nv_bfloat16 a, __nv_bfloat16 b) {
    __nv_bfloat162 t = __halves2bfloat162(a, b);
    uint32_t r; memcpy(&r, &t, 4); return r;
}
// tanh(x) = 1 - 2/(exp(2x)+1): 2 MUFU + 3 ALU, rel err ~1e-6; correct at +/-inf
__device__ __forceinline__ float tanh_fast(float x) {
    float t = __expf(2.f * x);
    return 1.f - __fdividef(2.f, t + 1.f);
}

// ---------------------------------------------------------------------------
// Kernel P1: g_pd[b,u] = h[b] @ W[:,u] + Wc_b[u]
// ---------------------------------------------------------------------------
__global__ void proj_dec_kernel(const float* __restrict__ h,
                                const float* __restrict__ W,
                                const float* __restrict__ Wc_b) {
    __shared__ float sh[D_];
    const int b = blockIdx.y;
    const int u = blockIdx.x * 128 + threadIdx.x;
    for (int i = threadIdx.x; i < D_; i += 128) sh[i] = h[b * D_ + i];
    __syncthreads();
    float a0 = 0.f, a1 = 0.f, a2 = 0.f, a3 = 0.f;
    #pragma unroll 8
    for (int k = 0; k < D_; k += 4) {
        a0 += sh[k + 0] * W[(size_t)(k + 0) * D_ + u];
        a1 += sh[k + 1] * W[(size_t)(k + 1) * D_ + u];
        a2 += sh[k + 2] * W[(size_t)(k + 2) * D_ + u];
        a3 += sh[k + 3] * W[(size_t)(k + 3) * D_ + u];
    }
    g_pd[b * D_ + u] = (a0 + a1) + (a2 + a3) + Wc_b[u];
}

// ---------------------------------------------------------------------------
// Kernel P2: bf16-split E -> g_Ehi/g_Elo
// ---------------------------------------------------------------------------
__global__ void esplit_kernel(const float* __restrict__ E) {
    size_t i = (size_t)blockIdx.x * 256 + threadIdx.x;
    const float4* E4 = (const float4*)E;
    float4 v0 = E4[2 * i], v1 = E4[2 * i + 1];
    float v[8] = {v0.x, v0.y, v0.z, v0.w, v1.x, v1.y, v1.z, v1.w};
    __nv_bfloat16 h[8], l[8];
    #pragma unroll
    for (int j = 0; j < 8; j++) {
        h[j] = __float2bfloat16_rn(v[j]);
        l[j] = __float2bfloat16_rn(v[j] - __bfloat162float(h[j]));
    }
    uint4 wh = {pk(h[0], h[1]), pk(h[2], h[3]), pk(h[4], h[5]), pk(h[6], h[7])};
    uint4 wl = {pk(l[0], l[1]), pk(l[2], l[3]), pk(l[4], l[5]), pk(l[6], l[7])};
    ((uint4*)g_Ehi)[i] = wh;
    ((uint4*)g_Elo)[i] = wl;
}

// ---------------------------------------------------------------------------
// Kernel P3: transpose + bf16-split U:  g_Uhi/g_Ulo[u][d]
// ---------------------------------------------------------------------------
__global__ void usplit_kernel(const float* __restrict__ U) {
    __shared__ float t[32][33];
    const int u0 = blockIdx.x * 32, d0 = blockIdx.y * 32;
    const int tx = threadIdx.x, ty = threadIdx.y;   // 32 x 8
    #pragma unroll
    for (int r = 0; r < 32; r += 8)
        t[ty + r][tx] = U[(size_t)(d0 + ty + r) * D_ + u0 + tx];
    __syncthreads();
    #pragma unroll
    for (int r = 0; r < 32; r += 8) {
        float v = t[tx][ty + r];
        int u = u0 + ty + r, d = d0 + tx;
        __nv_bfloat16 hi = __float2bfloat16_rn(v);
        __nv_bfloat16 lo = __float2bfloat16_rn(v - __bfloat162float(hi));
        g_Uhi[(size_t)u * D_ + d] = hi;
        g_Ulo[(size_t)u * D_ + d] = lo;
    }
}

// ---------------------------------------------------------------------------
// Kernel B: HMMA score GEMM + fused tanh.V epilogue (partial over u-block).
// CTA = 128 s x 256 u (2 n-chunks of 128), K in 32-wide chunks, 3-stage
// cp.async pipeline, 256 threads (8 warps, warp tile 64x32, 2 CTAs/SM).
// grid = (4 u-blocks, 512 bs-tiles); u fastest -> E-slice shared in L2.
// ---------------------------------------------------------------------------
#define KC     32
#define STAGE  32768          // A: 16KB (128x[hi32|lo32]), B: 16KB
#define NITER  64             // 2 n-chunks * 32 k-chunks

__global__ __launch_bounds__(256, 2)
void score_mma_kernel(const float* __restrict__ cov,
                      const float* __restrict__ Wc_w,
                      const float* __restrict__ Vv) {
    extern __shared__ __align__(128) char dyn[];
    __shared__ float s_pd[256], s_wc[256], s_v[256];
    __shared__ float red[4][128];

    const int tid = threadIdx.x, lane = tid & 31, wid = tid >> 5;
    const int warp_m = wid >> 2, warp_n = wid & 3;
    const int wm0 = warp_m * 64, wn0 = warp_n * 32;
    const int ublk = blockIdx.x;                 // 0..3
    const int b = blockIdx.y >> 4, s0 = (blockIdx.y & 15) * 128;
    const uint32_t sb = smem_u32(dyn);

    {
        int u = ublk * 256 + tid;
        s_pd[tid] = g_pd[b * D_ + u];
        s_wc[tid] = Wc_w[u];
        s_v[tid]  = Vv[u];
    }

    const __nv_bfloat16* Eh = g_Ehi + (size_t)(b * S_ + s0) * D_;
    const __nv_bfloat16* El = g_Elo + (size_t)(b * S_ + s0) * D_;

    // ldmatrix per-thread geometry (validated R3)
    const int arow = ((lane >> 3) & 1) * 8 + (lane & 7);
    const int acol = (lane >> 4);
    const int brow = ((lane >> 4) & 1) * 8 + (lane & 7);
    const int bcol = (lane >> 3) & 1;

    float covr[4][2];
    #pragma unroll
    for (int mi = 0; mi < 4; mi++)
        #pragma unroll
        for (int h = 0; h < 2; h++)
            covr[mi][h] = cov[b * S_ + s0 + wm0 + mi * 16 + (lane >> 2) + 8 * h];

    float acc[4][4][4];
    #pragma unroll
    for (int mi = 0; mi < 4; mi++)
        #pragma unroll
        for (int ni = 0; ni < 4; ni++)
            #pragma unroll
            for (int q = 0; q < 4; q++) acc[mi][ni][q] = 0.f;
    float rs[4][2];
    #pragma unroll
    for (int mi = 0; mi < 4; mi++) { rs[mi][0] = 0.f; rs[mi][1] = 0.f; }

    auto load_tiles = [&](int it) {
        const int nb = it >> 5, kc = it & 31;
        const uint32_t stg = sb + (uint32_t)(it % 3) * STAGE;
        const __nv_bfloat16* Ehk = Eh + kc * KC;
        const __nv_bfloat16* Elk = El + kc * KC;
        const __nv_bfloat16* Uhk = g_Uhi + (size_t)((ublk * 256 + nb * 128)) * D_ + kc * KC;
        const __nv_bfloat16* Ulk = g_Ulo + (size_t)((ublk * 256 + nb * 128)) * D_ + kc * KC;
        #pragma unroll
        for (int i = 0; i < 4; i++) {           // A: 1024 x 16B chunks
            int id = tid + i * 256;
            int r = id >> 3, c = id & 7;
            uint32_t off = SW128((uint32_t)(r * 128 + c * 16));
            const void* src = (c < 4) ? (const void*)(Ehk + (size_t)r * D_ + c * 8)
                                      : (const void*)(Elk + (size_t)r * D_ + (c - 4) * 8);
            cpa16(stg + off, src);
        }
        #pragma unroll
        for (int i = 0; i < 4; i++) {           // B
            int id = tid + i * 256;
            int r = id >> 3, c = id & 7;
            uint32_t off = SW128((uint32_t)(r * 128 + c * 16));
            const void* src = (c < 4) ? (const void*)(Uhk + (size_t)r * D_ + c * 8)
                                      : (const void*)(Ulk + (size_t)r * D_ + (c - 4) * 8);
            cpa16(stg + 16384 + off, src);
        }
        asm volatile("cp.async.commit_group;" ::: "memory");
    };

    load_tiles(0);
    load_tiles(1);

    for (int it = 0; it < NITER; it++) {
        if (it + 1 < NITER)
            asm volatile("cp.async.wait_group 1;" ::: "memory");
        else
            asm volatile("cp.async.wait_group 0;" ::: "memory");
        __syncthreads();
        if (it + 2 < NITER) load_tiles(it + 2);

        const uint32_t stg = sb + (uint32_t)(it % 3) * STAGE;
        #pragma unroll
        for (int ks = 0; ks < 2; ks++) {
            uint32_t a[4][4], bh[2][4], bl[2][4];
            #pragma unroll
            for (int mi = 0; mi < 4; mi++) {    // A hi
                uint32_t off = (uint32_t)((wm0 + mi * 16 + arow) * 128 + ks * 32 + acol * 16);
                ldsm4(a[mi], stg + SW128(off));
            }
            #pragma unroll
            for (int np = 0; np < 2; np++) {    // B hi
                uint32_t off = (uint32_t)((wn0 + np * 16 + brow) * 128 + ks * 32 + bcol * 16);
                ldsm4(bh[np], stg + 16384 + SW128(off));
            }
            #pragma unroll
            for (int mi = 0; mi < 4; mi++)
                #pragma unroll
                for (int ni = 0; ni < 4; ni++)
                    mma16816(acc[mi][ni], a[mi], &bh[ni >> 1][(ni & 1) * 2]);
            #pragma unroll
            for (int np = 0; np < 2; np++) {    // B lo
                uint32_t off = (uint32_t)((wn0 + np * 16 + brow) * 128 + 64 + ks * 32 + bcol * 16);
                ldsm4(bl[np], stg + 16384 + SW128(off));
            }
            #pragma unroll
            for (int mi = 0; mi < 4; mi++)
                #pragma unroll
                for (int ni = 0; ni < 4; ni++)
                    mma16816(acc[mi][ni], a[mi], &bl[ni >> 1][(ni & 1) * 2]);
            #pragma unroll
            for (int mi = 0; mi < 4; mi++) {    // A lo (overwrite hi frags)
                uint32_t off = (uint32_t)((wm0 + mi * 16 + arow) * 128 + 64 + ks * 32 + acol * 16);
                ldsm4(a[mi], stg + SW128(off));
            }
            #pragma unroll
            for (int mi = 0; mi < 4; mi++)
                #pragma unroll
                for (int ni = 0; ni < 4; ni++)
                    mma16816(acc[mi][ni], a[mi], &bh[ni >> 1][(ni & 1) * 2]);
        }

        if ((it & 31) == 31) {                  // epilogue for this n-chunk of 128
            const int nb = it >> 5;
            #pragma unroll
            for (int mi = 0; mi < 4; mi++)
                #pragma unroll
                for (int ni = 0; ni < 4; ni++)
                    #pragma unroll
                    for (int h = 0; h < 2; h++)
                        #pragma unroll
                        for (int j = 0; j < 2; j++) {
                            int u = nb * 128 + wn0 + ni * 8 + (lane & 3) * 2 + j;
                            float x = acc[mi][ni][h * 2 + j] + s_pd[u] + covr[mi][h] * s_wc[u];
                            rs[mi][h] += tanh_fast(x) * s_v[u];
                            acc[mi][ni][h * 2 + j] = 0.f;
                        }
        }
    }

    // reduce over lane quads (cols), then across warp_n via smem
    #pragma unroll
    for (int mi = 0; mi < 4; mi++)
        #pragma unroll
        for (int h = 0; h < 2; h++) {
            float v = rs[mi][h];
            v += __shfl_xor_sync(0xffffffffu, v, 1);
            v += __shfl_xor_sync(0xffffffffu, v, 2);
            if ((lane & 3) == 0)
                red[warp_n][wm0 + mi * 16 + (lane >> 2) + 8 * h] = v;
        }
    __syncthreads();
    if (tid < 128)
        g_spart[ublk * (B_ * S_) + b * S_ + s0 + tid] =
            red[0][tid] + red[1][tid] + red[2][tid] + red[3][tid];
}

// ---------------------------------------------------------------------------
// Kernel C: sum partials + masked softmax + renorm + coverage out
// ---------------------------------------------------------------------------
__global__ void softmax_kernel(const float* __restrict__ mask,
                               const float* __restrict__ cov,
                               float* __restrict__ out) {
    __shared__ float sh[S_];
    __shared__ float red[256];
    const int b = blockIdx.x, tid = threadIdx.x;

    float mx = -1e30f;
    for (int s = tid; s < S_; s += 256) {
        int i = b * S_ + s;
        float v = g_spart[i] + g_spart[B_ * S_ + i] +
                  g_spart[2 * B_ * S_ + i] + g_spart[3 * B_ * S_ + i];
        sh[s] = v;
        if (mask[i] > 0.f) mx = fmaxf(mx, v);
    }
    red[tid] = mx; __syncthreads();
    for (int o = 128; o; o >>= 1) {
        if (tid < o) red[tid] = fmaxf(red[tid], red[tid + o]);
        __syncthreads();
    }
    mx = red[0]; __syncthreads();

    float psum = 0.f;
    for (int s = tid; s < S_; s += 256) {
        float e = mask[b * S_ + s] * expf(sh[s] - mx);
        sh[s] = e;
        psum += e;
    }
    red[tid] = psum; __syncthreads();
    for (int o = 128; o; o >>= 1) {
        if (tid < o) red[tid] += red[tid + o];
        __syncthreads();
    }
    const float inv = 1.f / red[0];

    float* attn = out + B_ * D_;
    float* covo = out + B_ * D_ + B_ * S_;
    for (int s = tid; s < S_; s += 256) {
        float a = sh[s] * inv;
        attn[b * S_ + s] = a;
        covo[b * S_ + s] = cov[b * S_ + s] + a;
    }
}

// ---------------------------------------------------------------------------
// Kernel D: context[b,d] = sum_s attn[b,s] * E[b,s,d]   (float4 loads)
// ---------------------------------------------------------------------------
__global__ void context_kernel(const float* __restrict__ E,
                               const float* __restrict__ out_attn,
                               float* __restrict__ ctx) {
    __shared__ float shA[S_];
    __shared__ float4 red4[256];
    const int b  = blockIdx.y;
    const int dq = threadIdx.x & 31;
    const int ts = threadIdx.x >> 5;   // 0..7
    const int d  = blockIdx.x * 128 + dq * 4;

    for (int s = threadIdx.x; s < S_; s += 256)
        shA[s] = out_attn[b * S_ + s];
    __syncthreads();

    float4 acc = {0.f, 0.f, 0.f, 0.f};
    #pragma unroll 4
    for (int s = ts; s < S_; s += 8) {
        float a = shA[s];
        float4 e = *(const float4*)(E + ((size_t)(b * S_ + s)) * D_ + d);
        acc.x += a * e.x; acc.y += a * e.y; acc.z += a * e.z; acc.w += a * e.w;
    }
    red4[threadIdx.x] = acc;
    __syncthreads();
    if (ts == 0) {
        float4 r = red4[dq];
        #pragma unroll
        for (int w = 1; w < 8; w++) {
            float4 t = red4[dq + w * 32];
            r.x += t.x; r.y += t.y; r.z += t.z; r.w += t.w;
        }
        *(float4*)(ctx + b * D_ + d) = r;
    }
}

// ---------------------------------------------------------------------------
extern "C" void kernel_launch(void* const* d_in, const int* in_sizes, int n_in,
                              void* d_out, int out_size) {
    const float* E    = (const float*)d_in[0];
    const float* mask = (const float*)d_in[1];
    const float* h    = (const float*)d_in[2];
    const float* cov  = (const float*)d_in[3];
    const float* W    = (const float*)d_in[4];
    const float* U    = (const float*)d_in[5];
    const float* Wc_w = (const float*)d_in[6];
    const float* Wc_b = (const float*)d_in[7];
    const float* V    = (const float*)d_in[8];
    float* out = (float*)d_out;

    cudaFuncSetAttribute(score_mma_kernel,
                         cudaFuncAttributeMaxDynamicSharedMemorySize, 3 * STAGE);

    esplit_kernel<<<32768, 256>>>(E);
    usplit_kernel<<<dim3(32, 32), dim3(32, 8)>>>(U);
    proj_dec_kernel<<<dim3(D_ / 128, B_), 128>>>(h, W, Wc_b);
    score_mma_kernel<<<dim3(4, 512), 256, 3 * STAGE>>>(cov, Wc_w, V);
    softmax_kernel<<<B_, 256>>>(mask, cov, out);
    context_kernel<<<dim3(8, B_), 256>>>(E, out + B_ * D_, out);
}